// round 1
// baseline (speedup 1.0000x reference)
#include <cuda_runtime.h>

typedef unsigned long long u64;

#define NBINS 4
#define NFEAT 48
#define KTOT  2048      // 128 samples * 16 (h,w) positions
#define NT    8         // batch rows per CTA
#define TLEN  154
#define OUTF  (NBINS * NFEAT)   // 192

// -------- scratch (static device globals: allowed) --------
__device__ float g_M[TLEN * 128];                    // DWT matrix, [t][s]
__device__ float g_Weff[NBINS * NFEAT * KTOT];       // folded weights [b][f][k]

__constant__ float c_dec_lo[8] = {
    -0.010597401784997278f,  0.032883011666982945f,  0.030841381835986965f,
    -0.18703481171888114f,  -0.02798376941698385f,   0.6308807679295904f,
     0.7148465705525415f,    0.23037781330885523f };
__constant__ float c_dec_hi[8] = {
    -0.23037781330885523f,   0.7148465705525415f,   -0.6308807679295904f,
    -0.02798376941698385f,   0.18703481171888114f,   0.030841381835986965f,
    -0.032883011666982945f, -0.010597401784997278f };

// -------- packed fp32x2 helpers (ptxas never emits these from C++) --------
__device__ __forceinline__ u64 ffma2(u64 a, u64 b, u64 c) {
    u64 d; asm("fma.rn.f32x2 %0, %1, %2, %3;" : "=l"(d) : "l"(a), "l"(b), "l"(c));
    return d;
}
__device__ __forceinline__ u64 fadd2(u64 a, u64 b) {
    u64 d; asm("add.rn.f32x2 %0, %1, %2;" : "=l"(d) : "l"(a), "l"(b));
    return d;
}
__device__ __forceinline__ u64 dup2(float x) {
    u64 d; asm("mov.b64 %0, {%1, %1};" : "=l"(d) : "f"(x));
    return d;
}
__device__ __forceinline__ float2 unpack2(u64 a) {
    float2 v; asm("mov.b64 {%0, %1}, %2;" : "=f"(v.x), "=f"(v.y) : "l"(a));
    return v;
}

// ============================================================
// Kernel 1: build the 154x128 DWT analysis matrix by pushing
// 128 unit impulses through the exact reference pipeline.
// Filters: y[i] = sum_u xp[2i+u] * rev(DEC)[u]  (XLA conv = cross-correlation,
// reference pre-reversed the filters, so index DEC[7-u]).
// Reflect padding (no edge repeat), single bounce suffices.
// ============================================================
__global__ void build_M_kernel() {
    int j = threadIdx.x;  // input position 0..127
    float lo[128];
    float nxt[67];
    for (int i = 0; i < 128; ++i) lo[i] = (i == j) ? 1.0f : 0.0f;

    const int Ns[4]    = {128, 67, 37, 22};
    const int outs[4]  = {67, 37, 22, 14};
    const int hioff[4] = {14, 81, 118, 140};
    // pads: p = 2*(out-1) - N + 8 -> {12,13,13,12}; left pad = p/2 = 6 at all levels
    const int pl = 6;

    for (int lev = 0; lev < 4; ++lev) {
        int N = Ns[lev], out = outs[lev];
        for (int i = 0; i < out; ++i) {
            float a0 = 0.0f, a1 = 0.0f;
            #pragma unroll
            for (int u = 0; u < 8; ++u) {
                int r = 2 * i + u - pl;
                if (r < 0) r = -r;
                else if (r >= N) r = 2 * N - 2 - r;
                float xv = lo[r];
                a0 += xv * c_dec_lo[7 - u];  // H0R[u] = DEC_LO[7-u]
                a1 += xv * c_dec_hi[7 - u];
            }
            nxt[i] = a0;
            g_M[(hioff[lev] + i) * 128 + j] = a1;
        }
        for (int i = 0; i < out; ++i) lo[i] = nxt[i];
    }
    for (int i = 0; i < 14; ++i) g_M[i * 128 + j] = lo[i];  // lo_4 at offset 0
}

// ============================================================
// Kernel 2: fold M into conv_w.
// Weff[b][f][k=(s*16+h*4+w)] = sum_t M[t][s] * conv_w[b,f,t,h,w]
// One block per (b,f); conv_w row (154*16 floats) cached in smem.
// ============================================================
__global__ void build_weff_kernel(const float* __restrict__ conv_w) {
    int bf = blockIdx.x;  // 0..191
    __shared__ float sw[TLEN * 16];
    for (int i = threadIdx.x; i < TLEN * 16; i += 256)
        sw[i] = conv_w[(size_t)bf * (TLEN * 16) + i];
    __syncthreads();

    #pragma unroll
    for (int r = 0; r < 8; ++r) {
        int k = threadIdx.x + 256 * r;
        int s = k >> 4, hw = k & 15;
        float acc = 0.0f;
        #pragma unroll 2
        for (int t = 0; t < TLEN; ++t)
            acc += g_M[t * 128 + s] * sw[t * 16 + hw];
        g_Weff[(size_t)bf * KTOT + k] = acc;
    }
}

// ============================================================
// Kernel 3: main. Grid (ntot/NT, NBINS), 256 threads, 64KB dyn smem.
// Phase 1: stream x (perfectly coalesced float4), 2x2 maxpool via
//          shfl.xor(2) row-pair combine, store to XOR-swizzled smem.
//          smem float addr(k,n) = (k*4 + ((n>>1) ^ ((k>>2)&3)))*2 + (n&1)
// Phase 2: 8 warps x 6 features; lane owns k-stripe; n-pairs packed
//          in f32x2; butterfly reduce; bias + leaky relu; store.
// ============================================================
__global__ __launch_bounds__(256, 2)
void dwt_main_kernel(const float* __restrict__ x,
                     const float* __restrict__ conv_b,
                     float* __restrict__ out, int ntot)
{
    extern __shared__ float sm[];  // 2048 k * 8 n = 16384 floats = 64KB
    const int tid = threadIdx.x;
    const int b   = blockIdx.y;
    const int n0  = blockIdx.x * NT;

    // ---------- Phase 1: maxpool into swizzled smem ----------
    for (int nl = 0; nl < NT; ++nl) {
        int nidx = n0 + nl;
        if (nidx >= ntot) break;
        const float4* xg = reinterpret_cast<const float4*>(
            x + ((size_t)nidx * 512 + (size_t)b * 128) * 64);
        int np  = nl >> 1;
        int hal = nl & 1;
        #pragma unroll
        for (int r = 0; r < 8; ++r) {
            int slot = tid + 256 * r;          // = t*16 + p*2 + qh
            float4 v = xg[slot];
            float a = fmaxf(v.x, v.y);         // candidates for w = 2*qh
            float c = fmaxf(v.z, v.w);         // candidates for w = 2*qh+1
            a = fmaxf(a, __shfl_xor_sync(0xffffffffu, a, 2));  // combine p, p^1
            c = fmaxf(c, __shfl_xor_sync(0xffffffffu, c, 2));
            if ((slot & 2) == 0) {             // p even -> owner of pooled row h=p/2
                int t  = slot >> 4;
                int h  = (slot >> 2) & 3;
                int qh = slot & 1;
                int k0 = t * 16 + h * 4 + 2 * qh;
                int x4 = (k0 >> 2) & 3;        // same for k0 and k0+1
                int sx = np ^ x4;
                sm[((k0 * 4 + sx) << 1) + hal]       = a;
                sm[(((k0 + 1) * 4 + sx) << 1) + hal] = c;
            }
        }
    }
    __syncthreads();

    // ---------- Phase 2: folded GEMV, f32x2 over n-pairs ----------
    const int warp = tid >> 5;
    const int lane = tid & 31;
    const float* Wb = g_Weff + ((size_t)(b * NFEAT + warp * 6)) * KTOT + lane;
    const int x4 = (lane >> 2) & 3;  // (k>>2)&3 depends only on lane bits 2..3

    u64 acc[6][4];
    #pragma unroll
    for (int f = 0; f < 6; ++f)
        #pragma unroll
        for (int p = 0; p < 4; ++p) acc[f][p] = 0ull;

    #pragma unroll 4
    for (int j = 0; j < 64; ++j) {
        int k = lane + 32 * j;
        u64 p2[4];
        #pragma unroll
        for (int np = 0; np < 4; ++np)
            p2[np] = *reinterpret_cast<const u64*>(sm + ((k * 4 + (np ^ x4)) << 1));
        #pragma unroll
        for (int f = 0; f < 6; ++f) {
            float wv = __ldg(Wb + f * KTOT + 32 * j);
            u64 w2 = dup2(wv);
            #pragma unroll
            for (int np = 0; np < 4; ++np)
                acc[f][np] = ffma2(w2, p2[np], acc[f][np]);
        }
    }

    // butterfly reduce across the 32 k-stripes
    #pragma unroll
    for (int off = 16; off; off >>= 1) {
        #pragma unroll
        for (int f = 0; f < 6; ++f)
            #pragma unroll
            for (int np = 0; np < 4; ++np)
                acc[f][np] = fadd2(acc[f][np],
                                   __shfl_xor_sync(0xffffffffu, acc[f][np], off));
    }

    if (lane == 0) {
        #pragma unroll
        for (int f = 0; f < 6; ++f) {
            int fg = warp * 6 + f;
            float bias = conv_b[b * NFEAT + fg];
            #pragma unroll
            for (int np = 0; np < 4; ++np) {
                float2 v = unpack2(acc[f][np]);
                int na = n0 + 2 * np;
                float ya = v.x + bias; ya = (ya > 0.0f) ? ya : 0.02f * ya;
                float yb = v.y + bias; yb = (yb > 0.0f) ? yb : 0.02f * yb;
                if (na < ntot)     out[(size_t)na * OUTF + b * NFEAT + fg] = ya;
                if (na + 1 < ntot) out[(size_t)(na + 1) * OUTF + b * NFEAT + fg] = yb;
            }
        }
    }
}

// ============================================================
extern "C" void kernel_launch(void* const* d_in, const int* in_sizes, int n_in,
                              void* d_out, int out_size)
{
    const float* x      = (const float*)d_in[0];  // (n,1,512,8,8)
    const float* conv_w = (const float*)d_in[1];  // (4,48,154,4,4)
    const float* conv_b = (const float*)d_in[2];  // (4,48)
    float* out = (float*)d_out;                   // (n,192)

    int ntot = in_sizes[0] / (512 * 64);

    build_M_kernel<<<1, 128>>>();
    build_weff_kernel<<<NBINS * NFEAT, 256>>>(conv_w);

    cudaFuncSetAttribute(dwt_main_kernel,
                         cudaFuncAttributeMaxDynamicSharedMemorySize, 65536);
    dim3 grid((ntot + NT - 1) / NT, NBINS);
    dwt_main_kernel<<<grid, 256, 65536>>>(x, conv_b, out, ntot);
}

// round 2
// speedup vs baseline: 1.0249x; 1.0249x over previous
#include <cuda_runtime.h>

typedef unsigned long long u64;

#define NBINS 4
#define NFEAT 48
#define KTOT  2048      // 128 samples * 16 (h,w)
#define NT    16        // batch rows per CTA
#define TLEN  154
#define OUTF  (NBINS * NFEAT)   // 192

__device__ float g_M[TLEN * 128];               // DWT matrix [t][s]
__device__ float g_Weff[NBINS * NFEAT * KTOT];  // folded weights [b][f][k]

__constant__ float c_dec_lo[8] = {
    -0.010597401784997278f,  0.032883011666982945f,  0.030841381835986965f,
    -0.18703481171888114f,  -0.02798376941698385f,   0.6308807679295904f,
     0.7148465705525415f,    0.23037781330885523f };
__constant__ float c_dec_hi[8] = {
    -0.23037781330885523f,   0.7148465705525415f,   -0.6308807679295904f,
    -0.02798376941698385f,   0.18703481171888114f,   0.030841381835986965f,
    -0.032883011666982945f, -0.010597401784997278f };

// ---- packed fp32x2 helpers ----
__device__ __forceinline__ u64 ffma2(u64 a, u64 b, u64 c) {
    u64 d; asm("fma.rn.f32x2 %0, %1, %2, %3;" : "=l"(d) : "l"(a), "l"(b), "l"(c));
    return d;
}
__device__ __forceinline__ u64 fadd2(u64 a, u64 b) {
    u64 d; asm("add.rn.f32x2 %0, %1, %2;" : "=l"(d) : "l"(a), "l"(b));
    return d;
}
__device__ __forceinline__ u64 dup2(float x) {
    u64 d; asm("mov.b64 %0, {%1, %1};" : "=l"(d) : "f"(x));
    return d;
}
__device__ __forceinline__ float2 unpack2(u64 a) {
    float2 v; asm("mov.b64 {%0, %1}, %2;" : "=f"(v.x), "=f"(v.y) : "l"(a));
    return v;
}

__device__ __forceinline__ int refl(int r, int N) {
    if (r < 0) r = -r;
    else if (r >= N) r = 2 * N - 2 - r;
    return r;
}

// ============================================================
// Kernel 1: build 154x128 DWT matrix, all level buffers in SMEM
// (no local-memory spills). 256 threads, 1 block.
// Levels: N {128,67,37,22} -> out {67,37,22,14}; left pad 6 always;
// concat offsets: lo4 @0, hi1 @14, hi2 @81, hi3 @118, hi4 @140.
// ============================================================
__global__ void build_M_kernel() {
    extern __shared__ float smA[];        // A: 67*128, B: 37*128
    float* A = smA;
    float* B = smA + 67 * 128;
    const int tid = threadIdx.x;

    // ---- level 1 from implicit identity ----
    for (int idx = tid; idx < 67 * 128; idx += 256) {
        int i = idx >> 7, j = idx & 127;
        float a0 = 0.0f, a1 = 0.0f;
        #pragma unroll
        for (int u = 0; u < 8; ++u) {
            int r = refl(2 * i + u - 6, 128);
            if (r == j) { a0 += c_dec_lo[7 - u]; a1 += c_dec_hi[7 - u]; }
        }
        A[idx] = a0;
        g_M[(14 + i) * 128 + j] = a1;
    }
    __syncthreads();

    // ---- level 2: A(67) -> B(37), hi @81 ----
    for (int idx = tid; idx < 37 * 128; idx += 256) {
        int i = idx >> 7, j = idx & 127;
        float a0 = 0.0f, a1 = 0.0f;
        #pragma unroll
        for (int u = 0; u < 8; ++u) {
            int r = refl(2 * i + u - 6, 67);
            float xv = A[r * 128 + j];
            a0 += xv * c_dec_lo[7 - u];
            a1 += xv * c_dec_hi[7 - u];
        }
        B[idx] = a0;
        g_M[(81 + i) * 128 + j] = a1;
    }
    __syncthreads();

    // ---- level 3: B(37) -> A(22), hi @118 ----
    for (int idx = tid; idx < 22 * 128; idx += 256) {
        int i = idx >> 7, j = idx & 127;
        float a0 = 0.0f, a1 = 0.0f;
        #pragma unroll
        for (int u = 0; u < 8; ++u) {
            int r = refl(2 * i + u - 6, 37);
            float xv = B[r * 128 + j];
            a0 += xv * c_dec_lo[7 - u];
            a1 += xv * c_dec_hi[7 - u];
        }
        A[idx] = a0;
        g_M[(118 + i) * 128 + j] = a1;
    }
    __syncthreads();

    // ---- level 4: A(22) -> lo @0 (14 rows), hi @140 ----
    for (int idx = tid; idx < 14 * 128; idx += 256) {
        int i = idx >> 7, j = idx & 127;
        float a0 = 0.0f, a1 = 0.0f;
        #pragma unroll
        for (int u = 0; u < 8; ++u) {
            int r = refl(2 * i + u - 6, 22);
            float xv = A[r * 128 + j];
            a0 += xv * c_dec_lo[7 - u];
            a1 += xv * c_dec_hi[7 - u];
        }
        g_M[i * 128 + j] = a0;
        g_M[(140 + i) * 128 + j] = a1;
    }
}

// ============================================================
// Kernel 2: Weff[b][f][k] = sum_t M[t][k>>4] * conv_w[b,f,t,k&15]
// grid (192, 8): block = (bf, k-chunk of 256). SMEM-tiled.
// ============================================================
__global__ void build_weff_kernel(const float* __restrict__ conv_w) {
    const int bf = blockIdx.x;
    const int kc = blockIdx.y;
    __shared__ float Ms[TLEN * 16];
    __shared__ float Ws[TLEN * 16];
    const int tid = threadIdx.x;

    for (int i = tid; i < TLEN * 16; i += 256) {
        int t = i >> 4, c = i & 15;
        Ms[i] = g_M[t * 128 + kc * 16 + c];
        Ws[i] = conv_w[(size_t)bf * (TLEN * 16) + i];
    }
    __syncthreads();

    const int sl = tid >> 4;   // (k>>4)&15
    const int hw = tid & 15;   // k&15
    float acc = 0.0f;
    #pragma unroll 7
    for (int t = 0; t < TLEN; ++t)
        acc += Ms[t * 16 + sl] * Ws[t * 16 + hw];
    g_Weff[(size_t)bf * KTOT + kc * 256 + tid] = acc;
}

// ============================================================
// Kernel 3: main. Grid (ntot/16, 4), 256 threads, 128KB smem, 1 CTA/SM.
// SMEM layout (floats): addr(k, nl) = np*4096 + 2*khat + hal
//   np = nl>>1, hal = nl&1, khat = k ^ ((k>>4)&1)
// Phase 1 stores n-parity pairs as STS.64 -> 16 distinct banks (CF).
// Phase 2: lane owns k-stripe; 8 LDS.64 (one per np plane) per j,
// 6 scalar weight LDGs + dup, 48 FFMA2; butterfly f32x2 reduce.
// ============================================================
__global__ __launch_bounds__(256, 1)
void dwt_main_kernel(const float* __restrict__ x,
                     const float* __restrict__ conv_b,
                     float* __restrict__ out, int ntot)
{
    extern __shared__ float sm[];  // 2048 k * 16 n = 32768 floats = 128KB
    const int tid = threadIdx.x;
    const int b   = blockIdx.y;
    const int n0  = blockIdx.x * NT;

    // ---------- Phase 1: maxpool into swizzled smem ----------
    #pragma unroll 1
    for (int np = 0; np < NT / 2; ++np) {
        int ne = n0 + 2 * np;
        if (ne >= ntot) break;
        int no = (ne + 1 < ntot) ? (ne + 1) : ne;
        const float4* xg0 = reinterpret_cast<const float4*>(
            x + ((size_t)ne * 512 + (size_t)b * 128) * 64);
        const float4* xg1 = reinterpret_cast<const float4*>(
            x + ((size_t)no * 512 + (size_t)b * 128) * 64);
        float* smp = sm + np * 4096;
        #pragma unroll
        for (int r = 0; r < 8; ++r) {
            int slot = tid + 256 * r;      // = t*16 + row*2 + half
            float4 v0 = xg0[slot];
            float4 v1 = xg1[slot];
            float a0 = fmaxf(v0.x, v0.y), c0 = fmaxf(v0.z, v0.w);
            float a1 = fmaxf(v1.x, v1.y), c1 = fmaxf(v1.z, v1.w);
            a0 = fmaxf(a0, __shfl_xor_sync(0xffffffffu, a0, 2));
            c0 = fmaxf(c0, __shfl_xor_sync(0xffffffffu, c0, 2));
            a1 = fmaxf(a1, __shfl_xor_sync(0xffffffffu, a1, 2));
            c1 = fmaxf(c1, __shfl_xor_sync(0xffffffffu, c1, 2));
            if ((slot & 2) == 0) {         // row even -> owner of pooled row
                int t  = slot >> 4;
                int h  = (slot >> 2) & 3;
                int qh = slot & 1;
                int k0 = t * 16 + h * 4 + 2 * qh;   // even
                int tp = t & 1;
                int kh0 = k0 ^ tp;
                int kh1 = (k0 + 1) ^ tp;
                *reinterpret_cast<float2*>(smp + 2 * kh0) = make_float2(a0, a1);
                *reinterpret_cast<float2*>(smp + 2 * kh1) = make_float2(c0, c1);
            }
        }
    }
    __syncthreads();

    // ---------- Phase 2: folded GEMV over f32x2 n-pairs ----------
    const int warp = tid >> 5;
    const int lane = tid & 31;
    const float* Wb = g_Weff + ((size_t)(b * NFEAT + warp * 6)) * KTOT + lane;
    const int tpar = (lane >> 4) & 1;   // ((k)>>4)&1 for k = lane+32j

    u64 acc[6][NT / 2];
    #pragma unroll
    for (int f = 0; f < 6; ++f)
        #pragma unroll
        for (int p = 0; p < NT / 2; ++p) acc[f][p] = 0ull;

    #pragma unroll 2
    for (int j = 0; j < 64; ++j) {
        int k  = lane + 32 * j;
        int kh = k ^ tpar;
        const float* smk = sm + 2 * kh;
        u64 p2[NT / 2];
        #pragma unroll
        for (int pp = 0; pp < NT / 2; ++pp)
            p2[pp] = *reinterpret_cast<const u64*>(smk + pp * 4096);
        #pragma unroll
        for (int f = 0; f < 6; ++f) {
            float wv = __ldg(Wb + f * KTOT + 32 * j);
            u64 w2 = dup2(wv);
            #pragma unroll
            for (int pp = 0; pp < NT / 2; ++pp)
                acc[f][pp] = ffma2(w2, p2[pp], acc[f][pp]);
        }
    }

    // butterfly reduce across the 32 k-stripes
    #pragma unroll
    for (int off = 16; off; off >>= 1) {
        #pragma unroll
        for (int f = 0; f < 6; ++f)
            #pragma unroll
            for (int pp = 0; pp < NT / 2; ++pp)
                acc[f][pp] = fadd2(acc[f][pp],
                                   __shfl_xor_sync(0xffffffffu, acc[f][pp], off));
    }

    if (lane == 0) {
        #pragma unroll
        for (int f = 0; f < 6; ++f) {
            int fg = warp * 6 + f;
            float bias = conv_b[b * NFEAT + fg];
            #pragma unroll
            for (int pp = 0; pp < NT / 2; ++pp) {
                float2 v = unpack2(acc[f][pp]);
                int na = n0 + 2 * pp;
                float ya = v.x + bias; ya = (ya > 0.0f) ? ya : 0.02f * ya;
                float yb = v.y + bias; yb = (yb > 0.0f) ? yb : 0.02f * yb;
                if (na < ntot)     out[(size_t)na * OUTF + b * NFEAT + fg] = ya;
                if (na + 1 < ntot) out[(size_t)(na + 1) * OUTF + b * NFEAT + fg] = yb;
            }
        }
    }
}

// ============================================================
extern "C" void kernel_launch(void* const* d_in, const int* in_sizes, int n_in,
                              void* d_out, int out_size)
{
    const float* x      = (const float*)d_in[0];  // (n,1,512,8,8)
    const float* conv_w = (const float*)d_in[1];  // (4,48,154,4,4)
    const float* conv_b = (const float*)d_in[2];  // (4,48)
    float* out = (float*)d_out;                   // (n,192)

    int ntot = in_sizes[0] / (512 * 64);

    int mSmem = (67 * 128 + 37 * 128) * 4;  // 53248 B
    cudaFuncSetAttribute(build_M_kernel,
                         cudaFuncAttributeMaxDynamicSharedMemorySize, mSmem);
    build_M_kernel<<<1, 256, mSmem>>>();

    dim3 wgrid(NBINS * NFEAT, KTOT / 256);
    build_weff_kernel<<<wgrid, 256>>>(conv_w);

    cudaFuncSetAttribute(dwt_main_kernel,
                         cudaFuncAttributeMaxDynamicSharedMemorySize, 131072);
    dim3 grid((ntot + NT - 1) / NT, NBINS);
    dwt_main_kernel<<<grid, 256, 131072>>>(x, conv_b, out, ntot);
}

// round 3
// speedup vs baseline: 1.2019x; 1.1726x over previous
#include <cuda_runtime.h>

typedef unsigned long long u64;

#define NBINS  4
#define NFEAT  48
#define KTOT   2048
#define NT     16          // batch rows per unit
#define TLEN   154
#define OUTF   (NBINS * NFEAT)
#define NCTAS  148
#define CHUNKF 16384       // floats per buffer: 1024 k * 16 n

__device__ float g_Weff[NBINS * NFEAT * KTOT];  // [bf][k]

__constant__ float c_dec_lo[8] = {
    -0.010597401784997278f,  0.032883011666982945f,  0.030841381835986965f,
    -0.18703481171888114f,  -0.02798376941698385f,   0.6308807679295904f,
     0.7148465705525415f,    0.23037781330885523f };
__constant__ float c_dec_hi[8] = {
    -0.23037781330885523f,   0.7148465705525415f,   -0.6308807679295904f,
    -0.02798376941698385f,   0.18703481171888114f,   0.030841381835986965f,
    -0.032883011666982945f, -0.010597401784997278f };

__device__ __forceinline__ u64 ffma2(u64 a, u64 b, u64 c) {
    u64 d; asm("fma.rn.f32x2 %0, %1, %2, %3;" : "=l"(d) : "l"(a), "l"(b), "l"(c));
    return d;
}
__device__ __forceinline__ u64 fadd2(u64 a, u64 b) {
    u64 d; asm("add.rn.f32x2 %0, %1, %2;" : "=l"(d) : "l"(a), "l"(b));
    return d;
}
__device__ __forceinline__ u64 dup2(float x) {
    u64 d; asm("mov.b64 %0, {%1, %1};" : "=l"(d) : "f"(x));
    return d;
}
__device__ __forceinline__ float2 unpack2(u64 a) {
    float2 v; asm("mov.b64 {%0, %1}, %2;" : "=f"(v.x), "=f"(v.y) : "l"(a));
    return v;
}
__device__ __forceinline__ int refl(int r, int N) {
    if (r < 0) r = -r;
    else if (r >= N) r = 2 * N - 2 - r;
    return r;
}

// ============================================================
// Fused weight builder. Block (bf, kc): computes the 16 needed
// columns of the 154x128 DWT matrix M (impulse responses for
// input positions j = kc*16 + sl) entirely in smem, then folds:
//   Weff[bf][kc*256 + tid] = sum_t M[t][tid>>4] * conv_w[bf][t][tid&15]
// Levels: N {128,67,37,22} -> out {67,37,22,14}; left pad 6;
// concat: lo4 @0, hi1 @14, hi2 @81, hi3 @118, hi4 @140.
// ============================================================
__global__ void build_weff_fused(const float* __restrict__ conv_w) {
    __shared__ float A[68 * 16];
    __shared__ float B[38 * 16];
    __shared__ float Mt[TLEN * 16];
    __shared__ float Ws[TLEN * 16];
    const int tid = threadIdx.x;          // 256
    const int bf = blockIdx.x;
    const int kc = blockIdx.y;

    for (int i = tid; i < TLEN * 16; i += 256)
        Ws[i] = conv_w[(size_t)bf * (TLEN * 16) + i];

    const int sl = tid & 15;
    const int ip = tid >> 4;              // 16 i-threads per column
    const int j  = kc * 16 + sl;          // impulse position

    // Level 1 (implicit identity input, N=128)
    for (int i = ip; i < 67; i += 16) {
        float a0 = 0.0f, a1 = 0.0f;
        #pragma unroll
        for (int u = 0; u < 8; ++u) {
            int r = refl(2 * i + u - 6, 128);
            if (r == j) { a0 += c_dec_lo[7 - u]; a1 += c_dec_hi[7 - u]; }
        }
        A[i * 16 + sl] = a0;
        Mt[(14 + i) * 16 + sl] = a1;
    }
    __syncthreads();
    // Level 2: A(67) -> B(37)
    for (int i = ip; i < 37; i += 16) {
        float a0 = 0.0f, a1 = 0.0f;
        #pragma unroll
        for (int u = 0; u < 8; ++u) {
            int r = refl(2 * i + u - 6, 67);
            float xv = A[r * 16 + sl];
            a0 += xv * c_dec_lo[7 - u];
            a1 += xv * c_dec_hi[7 - u];
        }
        B[i * 16 + sl] = a0;
        Mt[(81 + i) * 16 + sl] = a1;
    }
    __syncthreads();
    // Level 3: B(37) -> A(22)
    for (int i = ip; i < 22; i += 16) {
        float a0 = 0.0f, a1 = 0.0f;
        #pragma unroll
        for (int u = 0; u < 8; ++u) {
            int r = refl(2 * i + u - 6, 37);
            float xv = B[r * 16 + sl];
            a0 += xv * c_dec_lo[7 - u];
            a1 += xv * c_dec_hi[7 - u];
        }
        A[i * 16 + sl] = a0;
        Mt[(118 + i) * 16 + sl] = a1;
    }
    __syncthreads();
    // Level 4: A(22) -> lo(14) @0, hi @140
    for (int i = ip; i < 14; i += 16) {
        float a0 = 0.0f, a1 = 0.0f;
        #pragma unroll
        for (int u = 0; u < 8; ++u) {
            int r = refl(2 * i + u - 6, 22);
            float xv = A[r * 16 + sl];
            a0 += xv * c_dec_lo[7 - u];
            a1 += xv * c_dec_hi[7 - u];
        }
        Mt[i * 16 + sl] = a0;
        Mt[(140 + i) * 16 + sl] = a1;
    }
    __syncthreads();

    // Fold
    const int scol = tid >> 4;
    const int hw   = tid & 15;
    float acc = 0.0f;
    #pragma unroll 7
    for (int t = 0; t < TLEN; ++t)
        acc += Mt[t * 16 + scol] * Ws[t * 16 + hw];
    g_Weff[(size_t)bf * KTOT + kc * 256 + tid] = acc;
}

// ============================================================
// Producer: maxpool one k-chunk (1024 k) of one 16-batch group
// into swizzled smem buffer. 128 threads (warps 8..11).
// Layout (floats): buf[np*2048 + 2*(kc ^ ((kc>>4)&1)) + hal]
// ============================================================
__device__ __forceinline__ void produce(float* __restrict__ buf,
                                        const float* __restrict__ x,
                                        int b, int g, int chunk,
                                        int ntot, int ptid)
{
    const int n0 = g * NT;
    #pragma unroll 1
    for (int np = 0; np < 8; ++np) {
        int ne = n0 + 2 * np;
        int no = ne + 1;
        if (ne >= ntot) ne = ntot - 1;
        if (no >= ntot) no = ntot - 1;
        const float4* xg0 = reinterpret_cast<const float4*>(
            x + ((size_t)ne * 512 + b * 128 + chunk * 64) * 64);
        const float4* xg1 = reinterpret_cast<const float4*>(
            x + ((size_t)no * 512 + b * 128 + chunk * 64) * 64);
        float* smp = buf + np * 2048;
        #pragma unroll
        for (int r = 0; r < 8; ++r) {
            int slot = ptid + 128 * r;        // t_local*16 + row*2 + half
            float4 v0 = xg0[slot];
            float4 v1 = xg1[slot];
            float a0 = fmaxf(v0.x, v0.y), c0 = fmaxf(v0.z, v0.w);
            float a1 = fmaxf(v1.x, v1.y), c1 = fmaxf(v1.z, v1.w);
            a0 = fmaxf(a0, __shfl_xor_sync(0xffffffffu, a0, 2));
            c0 = fmaxf(c0, __shfl_xor_sync(0xffffffffu, c0, 2));
            a1 = fmaxf(a1, __shfl_xor_sync(0xffffffffu, a1, 2));
            c1 = fmaxf(c1, __shfl_xor_sync(0xffffffffu, c1, 2));
            if ((slot & 2) == 0) {
                int t  = slot >> 4;           // local t 0..63
                int h  = (slot >> 2) & 3;
                int qh = slot & 1;
                int k0 = t * 16 + h * 4 + 2 * qh;
                int tp = t & 1;
                *reinterpret_cast<float2*>(smp + 2 * (k0 ^ tp))       = make_float2(a0, a1);
                *reinterpret_cast<float2*>(smp + 2 * ((k0 + 1) ^ tp)) = make_float2(c0, c1);
            }
        }
    }
}

// ============================================================
// Main kernel: persistent, warp-specialized, double buffered.
// grid = 148 CTAs (1/SM), 384 threads, 128KB dyn smem.
// warps 0..7 : consumers (6 features each), warps 8..11: producers.
// Unit = (b, g): 16 batch rows, full k=2048 = 2 chunk-steps.
// ============================================================
__global__ __launch_bounds__(384, 1)
void dwt_main_kernel(const float* __restrict__ x,
                     const float* __restrict__ conv_b,
                     float* __restrict__ out, int ntot, int groups)
{
    extern __shared__ float sm[];  // 2 * 16384 floats
    const int tid  = threadIdx.x;
    const int warp = tid >> 5;
    const int lane = tid & 31;
    const int cta  = blockIdx.x;
    const int G    = gridDim.x;
    const int nunits = NBINS * groups;
    const int myUnits = (cta < nunits) ? ((nunits - 1 - cta) / G + 1) : 0;
    const int totalSteps = 2 * myUnits;

    u64 acc[6][8];
    #pragma unroll
    for (int f = 0; f < 6; ++f)
        #pragma unroll
        for (int p = 0; p < 8; ++p) acc[f][p] = 0ull;

    // prologue: producers fill buf0 with (unit0, chunk0)
    if (warp >= 8 && totalSteps > 0) {
        int u = cta;
        produce(sm, x, u / groups, u % groups, 0, ntot, tid - 256);
    }
    __syncthreads();

    for (int s = 0; s < totalSteps; ++s) {
        const int u = cta + G * (s >> 1);
        const int b = u / groups;
        const int g = u % groups;
        const int chunk = s & 1;
        float* buf = sm + (s & 1) * CHUNKF;

        if (warp < 8) {
            // -------- consumer: accumulate 1024-k chunk --------
            const float* Wb = g_Weff + ((size_t)(b * NFEAT + warp * 6)) * KTOT
                              + chunk * 1024 + lane;
            const int tpar = (lane >> 4) & 1;
            const float* smk = buf + 2 * (lane ^ tpar);

            float wv[6];
            #pragma unroll
            for (int f = 0; f < 6; ++f) wv[f] = __ldg(Wb + f * KTOT);

            #pragma unroll 1
            for (int jl = 0; jl < 32; ++jl) {
                float wn[6];
                if (jl < 31) {
                    #pragma unroll
                    for (int f = 0; f < 6; ++f)
                        wn[f] = __ldg(Wb + f * KTOT + 32 * (jl + 1));
                }
                u64 p2[8];
                #pragma unroll
                for (int pp = 0; pp < 8; ++pp)
                    p2[pp] = *reinterpret_cast<const u64*>(smk + 64 * jl + pp * 2048);
                #pragma unroll
                for (int f = 0; f < 6; ++f) {
                    u64 w2 = dup2(wv[f]);
                    #pragma unroll
                    for (int pp = 0; pp < 8; ++pp)
                        acc[f][pp] = ffma2(w2, p2[pp], acc[f][pp]);
                }
                if (jl < 31) {
                    #pragma unroll
                    for (int f = 0; f < 6; ++f) wv[f] = wn[f];
                }
            }

            if (chunk == 1) {
                // -------- epilogue: reduce + store + reset --------
                #pragma unroll
                for (int off = 16; off; off >>= 1)
                    #pragma unroll
                    for (int f = 0; f < 6; ++f)
                        #pragma unroll
                        for (int pp = 0; pp < 8; ++pp)
                            acc[f][pp] = fadd2(acc[f][pp],
                                __shfl_xor_sync(0xffffffffu, acc[f][pp], off));
                if (lane == 0) {
                    int n0 = g * NT;
                    #pragma unroll
                    for (int f = 0; f < 6; ++f) {
                        int fg = warp * 6 + f;
                        float bias = conv_b[b * NFEAT + fg];
                        #pragma unroll
                        for (int pp = 0; pp < 8; ++pp) {
                            float2 v = unpack2(acc[f][pp]);
                            int na = n0 + 2 * pp;
                            float ya = v.x + bias; ya = (ya > 0.0f) ? ya : 0.02f * ya;
                            float yb = v.y + bias; yb = (yb > 0.0f) ? yb : 0.02f * yb;
                            if (na < ntot)
                                out[(size_t)na * OUTF + b * NFEAT + fg] = ya;
                            if (na + 1 < ntot)
                                out[(size_t)(na + 1) * OUTF + b * NFEAT + fg] = yb;
                        }
                    }
                }
                #pragma unroll
                for (int f = 0; f < 6; ++f)
                    #pragma unroll
                    for (int pp = 0; pp < 8; ++pp) acc[f][pp] = 0ull;
            }
        } else {
            // -------- producer: fill the other buffer with step s+1 --------
            int s2 = s + 1;
            if (s2 < totalSteps) {
                int u2 = cta + G * (s2 >> 1);
                produce(sm + (s2 & 1) * CHUNKF, x,
                        u2 / groups, u2 % groups, s2 & 1, ntot, tid - 256);
            }
        }
        __syncthreads();
    }
}

// ============================================================
extern "C" void kernel_launch(void* const* d_in, const int* in_sizes, int n_in,
                              void* d_out, int out_size)
{
    const float* x      = (const float*)d_in[0];  // (n,1,512,8,8)
    const float* conv_w = (const float*)d_in[1];  // (4,48,154,4,4)
    const float* conv_b = (const float*)d_in[2];  // (4,48)
    float* out = (float*)d_out;                   // (n,192)

    int ntot   = in_sizes[0] / (512 * 64);
    int groups = (ntot + NT - 1) / NT;

    dim3 wgrid(NBINS * NFEAT, KTOT / 256);
    build_weff_fused<<<wgrid, 256>>>(conv_w);

    cudaFuncSetAttribute(dwt_main_kernel,
                         cudaFuncAttributeMaxDynamicSharedMemorySize, 2 * CHUNKF * 4);
    dwt_main_kernel<<<NCTAS, 384, 2 * CHUNKF * 4>>>(x, conv_b, out, ntot, groups);
}

// round 4
// speedup vs baseline: 1.2633x; 1.0512x over previous
#include <cuda_runtime.h>

typedef unsigned long long u64;

#define NBINS  4
#define NFEAT  48
#define KTOT   2048
#define NT     16            // batch rows per unit
#define TLEN   154
#define OUTF   (NBINS * NFEAT)
#define NCTAS  148
#define CHUNKF 16384         // floats per buffer: 1024 k * 16 n  (64KB)
#define NTHREADS 768         // 16 consumer warps + 8 producer warps

__device__ float g_Weff[NBINS * NFEAT * KTOT];  // [bf][k]

__constant__ float c_dec_lo[8] = {
    -0.010597401784997278f,  0.032883011666982945f,  0.030841381835986965f,
    -0.18703481171888114f,  -0.02798376941698385f,   0.6308807679295904f,
     0.7148465705525415f,    0.23037781330885523f };
__constant__ float c_dec_hi[8] = {
    -0.23037781330885523f,   0.7148465705525415f,   -0.6308807679295904f,
    -0.02798376941698385f,   0.18703481171888114f,   0.030841381835986965f,
    -0.032883011666982945f, -0.010597401784997278f };

__device__ __forceinline__ u64 ffma2(u64 a, u64 b, u64 c) {
    u64 d; asm("fma.rn.f32x2 %0, %1, %2, %3;" : "=l"(d) : "l"(a), "l"(b), "l"(c));
    return d;
}
__device__ __forceinline__ u64 fadd2(u64 a, u64 b) {
    u64 d; asm("add.rn.f32x2 %0, %1, %2;" : "=l"(d) : "l"(a), "l"(b));
    return d;
}
__device__ __forceinline__ u64 dup2(float x) {
    u64 d; asm("mov.b64 %0, {%1, %1};" : "=l"(d) : "f"(x));
    return d;
}
__device__ __forceinline__ float2 unpack2(u64 a) {
    float2 v; asm("mov.b64 {%0, %1}, %2;" : "=f"(v.x), "=f"(v.y) : "l"(a));
    return v;
}
__device__ __forceinline__ int refl(int r, int N) {
    if (r < 0) r = -r;
    else if (r >= N) r = 2 * N - 2 - r;
    return r;
}

// ============================================================
// Fused weight builder (unchanged from round 3; ~3us).
// Weff[bf][kc*256+tid] = sum_t M[t][tid>>4] * conv_w[bf][t][tid&15]
// ============================================================
__global__ void build_weff_fused(const float* __restrict__ conv_w) {
    __shared__ float A[68 * 16];
    __shared__ float B[38 * 16];
    __shared__ float Mt[TLEN * 16];
    __shared__ float Ws[TLEN * 16];
    const int tid = threadIdx.x;
    const int bf = blockIdx.x;
    const int kc = blockIdx.y;

    for (int i = tid; i < TLEN * 16; i += 256)
        Ws[i] = conv_w[(size_t)bf * (TLEN * 16) + i];

    const int sl = tid & 15;
    const int ip = tid >> 4;
    const int j  = kc * 16 + sl;

    for (int i = ip; i < 67; i += 16) {
        float a0 = 0.0f, a1 = 0.0f;
        #pragma unroll
        for (int u = 0; u < 8; ++u) {
            int r = refl(2 * i + u - 6, 128);
            if (r == j) { a0 += c_dec_lo[7 - u]; a1 += c_dec_hi[7 - u]; }
        }
        A[i * 16 + sl] = a0;
        Mt[(14 + i) * 16 + sl] = a1;
    }
    __syncthreads();
    for (int i = ip; i < 37; i += 16) {
        float a0 = 0.0f, a1 = 0.0f;
        #pragma unroll
        for (int u = 0; u < 8; ++u) {
            int r = refl(2 * i + u - 6, 67);
            float xv = A[r * 16 + sl];
            a0 += xv * c_dec_lo[7 - u];
            a1 += xv * c_dec_hi[7 - u];
        }
        B[i * 16 + sl] = a0;
        Mt[(81 + i) * 16 + sl] = a1;
    }
    __syncthreads();
    for (int i = ip; i < 22; i += 16) {
        float a0 = 0.0f, a1 = 0.0f;
        #pragma unroll
        for (int u = 0; u < 8; ++u) {
            int r = refl(2 * i + u - 6, 37);
            float xv = B[r * 16 + sl];
            a0 += xv * c_dec_lo[7 - u];
            a1 += xv * c_dec_hi[7 - u];
        }
        A[i * 16 + sl] = a0;
        Mt[(118 + i) * 16 + sl] = a1;
    }
    __syncthreads();
    for (int i = ip; i < 14; i += 16) {
        float a0 = 0.0f, a1 = 0.0f;
        #pragma unroll
        for (int u = 0; u < 8; ++u) {
            int r = refl(2 * i + u - 6, 22);
            float xv = A[r * 16 + sl];
            a0 += xv * c_dec_lo[7 - u];
            a1 += xv * c_dec_hi[7 - u];
        }
        Mt[i * 16 + sl] = a0;
        Mt[(140 + i) * 16 + sl] = a1;
    }
    __syncthreads();

    const int scol = tid >> 4;
    const int hw   = tid & 15;
    float acc = 0.0f;
    #pragma unroll 7
    for (int t = 0; t < TLEN; ++t)
        acc += Mt[t * 16 + scol] * Ws[t * 16 + hw];
    g_Weff[(size_t)bf * KTOT + kc * 256 + tid] = acc;
}

// ============================================================
// Producer: 8 warps (256 threads, ptid 0..255). One k-chunk
// (1024 k) x 16 n. Per np: 8 front-batched LDG.128, shfl-pool,
// swizzled STS.64. Layout: buf[np*2048 + 2*(k ^ (t&1)) + hal].
// ============================================================
__device__ __forceinline__ void produce(float* __restrict__ buf,
                                        const float* __restrict__ x,
                                        int b, int g, int chunk,
                                        int ntot, int ptid)
{
    const int n0 = g * NT;
    #pragma unroll 1
    for (int np = 0; np < 8; ++np) {
        int ne = n0 + 2 * np;
        int no = ne + 1;
        if (ne >= ntot) ne = ntot - 1;
        if (no >= ntot) no = ntot - 1;
        const float4* xg0 = reinterpret_cast<const float4*>(
            x + ((size_t)ne * 512 + b * 128 + chunk * 64) * 64);
        const float4* xg1 = reinterpret_cast<const float4*>(
            x + ((size_t)no * 512 + b * 128 + chunk * 64) * 64);
        float* smp = buf + np * 2048;

        float4 v0[4], v1[4];
        #pragma unroll
        for (int r = 0; r < 4; ++r) {
            v0[r] = xg0[ptid + 256 * r];
            v1[r] = xg1[ptid + 256 * r];
        }
        #pragma unroll
        for (int r = 0; r < 4; ++r) {
            int slot = ptid + 256 * r;       // t*16 + row*2 + half
            float a0 = fmaxf(v0[r].x, v0[r].y), c0 = fmaxf(v0[r].z, v0[r].w);
            float a1 = fmaxf(v1[r].x, v1[r].y), c1 = fmaxf(v1[r].z, v1[r].w);
            a0 = fmaxf(a0, __shfl_xor_sync(0xffffffffu, a0, 2));
            c0 = fmaxf(c0, __shfl_xor_sync(0xffffffffu, c0, 2));
            a1 = fmaxf(a1, __shfl_xor_sync(0xffffffffu, a1, 2));
            c1 = fmaxf(c1, __shfl_xor_sync(0xffffffffu, c1, 2));
            if ((slot & 2) == 0) {
                int t  = slot >> 4;
                int h  = (slot >> 2) & 3;
                int qh = slot & 1;
                int k0 = t * 16 + h * 4 + 2 * qh;
                int tp = t & 1;
                *reinterpret_cast<float2*>(smp + 2 * (k0 ^ tp))       = make_float2(a0, a1);
                *reinterpret_cast<float2*>(smp + 2 * ((k0 + 1) ^ tp)) = make_float2(c0, c1);
            }
        }
    }
}

// ============================================================
// Main: persistent, warp-specialized, double buffered.
// 148 CTAs x 768 threads, 128KB smem, <=85 regs.
// Warps 0..15: consumers (3 features each); 16..23: producers.
// ============================================================
__global__ __launch_bounds__(NTHREADS, 1)
void dwt_main_kernel(const float* __restrict__ x,
                     const float* __restrict__ conv_b,
                     float* __restrict__ out, int ntot, int groups)
{
    extern __shared__ float sm[];  // 2 * CHUNKF floats
    const int tid  = threadIdx.x;
    const int warp = tid >> 5;
    const int lane = tid & 31;
    const int cta  = blockIdx.x;
    const int G    = gridDim.x;
    const int nunits = NBINS * groups;
    const int myUnits = (cta < nunits) ? ((nunits - 1 - cta) / G + 1) : 0;
    const int totalSteps = 2 * myUnits;

    u64 acc[3][8];
    #pragma unroll
    for (int f = 0; f < 3; ++f)
        #pragma unroll
        for (int p = 0; p < 8; ++p) acc[f][p] = 0ull;

    if (warp >= 16 && totalSteps > 0) {
        int u = cta;
        produce(sm, x, u / groups, u % groups, 0, ntot, tid - 512);
    }
    __syncthreads();

    for (int s = 0; s < totalSteps; ++s) {
        const int u = cta + G * (s >> 1);
        const int b = u / groups;
        const int g = u % groups;
        const int chunk = s & 1;
        float* buf = sm + (s & 1) * CHUNKF;

        if (warp < 16) {
            // ---- consumer: 3 features, 1024-k chunk ----
            const float* Wb = g_Weff + ((size_t)(b * NFEAT + warp * 3)) * KTOT
                              + chunk * 1024 + lane;
            const int tpar = (lane >> 4) & 1;
            const float* smk = buf + 2 * (lane ^ tpar);

            float w0[3], w1[3];
            #pragma unroll
            for (int f = 0; f < 3; ++f) w0[f] = __ldg(Wb + f * KTOT);
            #pragma unroll
            for (int f = 0; f < 3; ++f) w1[f] = __ldg(Wb + f * KTOT + 32);

            #pragma unroll 1
            for (int jl = 0; jl < 32; jl += 2) {
                // even jl: use w0, prefetch jl+2 into w0
                {
                    u64 p2[8];
                    #pragma unroll
                    for (int pp = 0; pp < 8; ++pp)
                        p2[pp] = *reinterpret_cast<const u64*>(smk + 64 * jl + pp * 2048);
                    float wl0 = w0[0], wl1 = w0[1], wl2 = w0[2];
                    if (jl + 2 < 32) {
                        #pragma unroll
                        for (int f = 0; f < 3; ++f)
                            w0[f] = __ldg(Wb + f * KTOT + 32 * (jl + 2));
                    }
                    u64 d0 = dup2(wl0), d1 = dup2(wl1), d2 = dup2(wl2);
                    #pragma unroll
                    for (int pp = 0; pp < 8; ++pp) {
                        acc[0][pp] = ffma2(d0, p2[pp], acc[0][pp]);
                        acc[1][pp] = ffma2(d1, p2[pp], acc[1][pp]);
                        acc[2][pp] = ffma2(d2, p2[pp], acc[2][pp]);
                    }
                }
                // odd jl: use w1, prefetch jl+3 into w1
                {
                    u64 p2[8];
                    #pragma unroll
                    for (int pp = 0; pp < 8; ++pp)
                        p2[pp] = *reinterpret_cast<const u64*>(smk + 64 * (jl + 1) + pp * 2048);
                    float wl0 = w1[0], wl1 = w1[1], wl2 = w1[2];
                    if (jl + 3 < 32) {
                        #pragma unroll
                        for (int f = 0; f < 3; ++f)
                            w1[f] = __ldg(Wb + f * KTOT + 32 * (jl + 3));
                    }
                    u64 d0 = dup2(wl0), d1 = dup2(wl1), d2 = dup2(wl2);
                    #pragma unroll
                    for (int pp = 0; pp < 8; ++pp) {
                        acc[0][pp] = ffma2(d0, p2[pp], acc[0][pp]);
                        acc[1][pp] = ffma2(d1, p2[pp], acc[1][pp]);
                        acc[2][pp] = ffma2(d2, p2[pp], acc[2][pp]);
                    }
                }
            }

            if (chunk == 1) {
                // ---- epilogue: butterfly reduce + store + reset ----
                #pragma unroll
                for (int off = 16; off; off >>= 1)
                    #pragma unroll
                    for (int f = 0; f < 3; ++f)
                        #pragma unroll
                        for (int pp = 0; pp < 8; ++pp)
                            acc[f][pp] = fadd2(acc[f][pp],
                                __shfl_xor_sync(0xffffffffu, acc[f][pp], off));
                if (lane == 0) {
                    int n0 = g * NT;
                    #pragma unroll
                    for (int f = 0; f < 3; ++f) {
                        int fg = warp * 3 + f;
                        float bias = conv_b[b * NFEAT + fg];
                        #pragma unroll
                        for (int pp = 0; pp < 8; ++pp) {
                            float2 v = unpack2(acc[f][pp]);
                            int na = n0 + 2 * pp;
                            float ya = v.x + bias; ya = (ya > 0.0f) ? ya : 0.02f * ya;
                            float yb = v.y + bias; yb = (yb > 0.0f) ? yb : 0.02f * yb;
                            if (na < ntot)
                                out[(size_t)na * OUTF + b * NFEAT + fg] = ya;
                            if (na + 1 < ntot)
                                out[(size_t)(na + 1) * OUTF + b * NFEAT + fg] = yb;
                        }
                    }
                }
                #pragma unroll
                for (int f = 0; f < 3; ++f)
                    #pragma unroll
                    for (int pp = 0; pp < 8; ++pp) acc[f][pp] = 0ull;
            }
        } else {
            // ---- producer: fill the other buffer with step s+1 ----
            int s2 = s + 1;
            if (s2 < totalSteps) {
                int u2 = cta + G * (s2 >> 1);
                produce(sm + (s2 & 1) * CHUNKF, x,
                        u2 / groups, u2 % groups, s2 & 1, ntot, tid - 512);
            }
        }
        __syncthreads();
    }
}

// ============================================================
extern "C" void kernel_launch(void* const* d_in, const int* in_sizes, int n_in,
                              void* d_out, int out_size)
{
    const float* x      = (const float*)d_in[0];  // (n,1,512,8,8)
    const float* conv_w = (const float*)d_in[1];  // (4,48,154,4,4)
    const float* conv_b = (const float*)d_in[2];  // (4,48)
    float* out = (float*)d_out;                   // (n,192)

    int ntot   = in_sizes[0] / (512 * 64);
    int groups = (ntot + NT - 1) / NT;

    dim3 wgrid(NBINS * NFEAT, KTOT / 256);
    build_weff_fused<<<wgrid, 256>>>(conv_w);

    cudaFuncSetAttribute(dwt_main_kernel,
                         cudaFuncAttributeMaxDynamicSharedMemorySize, 2 * CHUNKF * 4);
    dwt_main_kernel<<<NCTAS, NTHREADS, 2 * CHUNKF * 4>>>(x, conv_b, out, ntot, groups);
}